// round 12
// baseline (speedup 1.0000x reference)
#include <cuda_runtime.h>

typedef unsigned long long ull;

#define NG 8           // batch groups (32 batches each)
#define NP 16          // column partitions (16 hidden cols each)
#define NBLK (NG*NP)   // 128 CTAs
#define NT 512         // threads per CTA (16 warps)
// smem floats: sWA 12288 + sWB 24576 + h0s 8192 + h1s 8192 + red 4608 (=2304 ull)
#define SM_FLOATS (12288+24576+8192+8192+4608)
#define SMEM_BYTES (SM_FLOATS*4)

// ---------------- static device scratch (no allocation) ----------------
__device__ float d_pA[NP*256*48];      // W_hh0 packed  [p][k][cp][gate*2+cl]
__device__ float d_pB[NP*256*96];      // W_ih1|W_hh1   [p][k][cp][gate*4+s*2+cl]
__device__ float d_pD[NP*256*48];      // Wd_hh packed like A
__device__ float d_xT[512*256];        // x transposed [t][b]
__device__ float d_h0g[2*NG*256*32];   // double-buffered layer0 h [par][g][col][b]
__device__ float d_h1g[2*NG*256*32];   // layer1 / decoder h
__device__ float d_partg[2*NP*NG*32];  // decoder partial y
__device__ unsigned int d_cnt[NG];     // group barrier counters

// ---------------- prep: reset barriers, pack weights, transpose x ----------------
__global__ void prep_kernel(const float* __restrict__ Whh0, const float* __restrict__ Wih1,
                            const float* __restrict__ Whh1, const float* __restrict__ Wdhh,
                            const float* __restrict__ x)
{
    int idx = blockIdx.x*blockDim.x + threadIdx.x;
    int stride = gridDim.x*blockDim.x;
    if (idx < NG) d_cnt[idx] = 0u;
    for (int i = idx; i < NP*256*48; i += stride) {
        int q = i % 6, cp = (i/6) & 7, k = (i/48) & 255, p = i/12288;
        int gate = q >> 1, cl = q & 1;
        int col = p*16 + cp*2 + cl;
        int src = (gate*256 + col)*256 + k;
        d_pA[i] = Whh0[src];
        d_pD[i] = Wdhh[src];
    }
    for (int i = idx; i < NP*256*96; i += stride) {
        int q = i % 12, cp = (i/12) & 7, k = (i/96) & 255, p = i/24576;
        int gate = q >> 2, s = (q >> 1) & 1, cl = q & 1;
        int col = p*16 + cp*2 + cl;
        int src = (gate*256 + col)*256 + k;
        d_pB[i] = s ? Whh1[src] : Wih1[src];
    }
    for (int i = idx; i < 512*256; i += stride)
        d_xT[i] = x[(i & 255)*512 + (i >> 8)];
    for (int i = idx; i < 2*NG*256*32; i += stride)
        d_h1g[i] = 0.0f;   // phase-0 refresh of h1 must read zeros
}

// ---------------- helpers ----------------
__device__ __forceinline__ ull splat2(float v){ ull r; asm("mov.b64 %0, {%1,%1};" : "=l"(r) : "f"(v)); return r; }
__device__ __forceinline__ void fma2(ull &d, ull a, ull b){ asm("fma.rn.f32x2 %0, %1, %2, %0;" : "+l"(d) : "l"(a), "l"(b)); }
__device__ __forceinline__ ull add2(ull a, ull b){ ull r; asm("add.rn.f32x2 %0, %1, %2;" : "=l"(r) : "l"(a), "l"(b)); return r; }
__device__ __forceinline__ float2 unp(ull v){ float2 f; asm("mov.b64 {%0,%1}, %2;" : "=f"(f.x), "=f"(f.y) : "l"(v)); return f; }
__device__ __forceinline__ float sigf(float v){ return 1.0f/(1.0f + __expf(-v)); }
__device__ __forceinline__ float tanh_(float v){
    float a = fabsf(v), e = __expf(-2.0f*a);
    float t = (1.0f - e)/(1.0f + e);
    return v < 0.0f ? -t : t;
}
// within-warp cross-quarter reduce (lane bit 4)
__device__ __forceinline__ ull shred(ull v){
    ull o = __shfl_xor_sync(0xffffffffu, v, 16);
    return add2(v, o);
}

// per-group barrier: release(prior stores) -> arrive -> spin -> acquire
__device__ __forceinline__ void gbar(int g, unsigned target){
    __threadfence();
    __syncthreads();
    if (threadIdx.x == 0) {
        atomicAdd(&d_cnt[g], 1u);
        while (*(volatile unsigned*)&d_cnt[g] < target) __nanosleep(16);
        __threadfence();
    }
    __syncthreads();
}

// ---------------- main persistent kernel ----------------
__global__ __launch_bounds__(NT, 1) void gru_main(
    const float* __restrict__ Wih0, const float* __restrict__ bih0, const float* __restrict__ bhh0,
    const float* __restrict__ bih1, const float* __restrict__ bhh1,
    const float* __restrict__ Wdih, const float* __restrict__ bdih, const float* __restrict__ bdhh,
    const float* __restrict__ Wo, const float* __restrict__ bo,
    float* __restrict__ out)
{
    extern __shared__ float sm[];
    float* sWA  = sm;                      // [256][8][6]   12288
    float* sWB  = sm + 12288;              // [256][8][12]  24576
    float* h0s  = sWB + 24576;             // [256][32]      8192
    float* h1s  = h0s + 8192;              // [256][32]      8192
    ull*   red  = (ull*)(h1s + 8192);      // [8][16][18]    2304 ull
    float* red2 = (float*)red;             // decoder alias: [32][8] floats (sync-guarded)

    const int p    = blockIdx.x & 15;
    const int g    = blockIdx.x >> 4;
    const int tid  = threadIdx.x;
    const int warp = tid >> 5;
    const int cp   = warp & 7;             // col pair 0..7
    const int kH   = warp >> 3;            // k half (warp-level)
    const int lane = tid & 31;
    const int kh   = lane >> 4;            // k quarter within half (lane-level)
    const int bp   = lane & 15;            // batch pair 0..15
    const int kbeg = (kH*2 + kh) << 6;     // 64-wide k quarter
    const int c0   = p*16 + cp*2;
    const bool epi = (kH == 0) && (kh == 0);   // 128 epilogue threads

    // stage weights + zero h tiles
    {
        const float4* a4 = (const float4*)(d_pA + p*12288);
        float4* da = (float4*)sWA;
        for (int i = tid; i < 3072; i += NT) da[i] = a4[i];
        const float4* b4 = (const float4*)(d_pB + p*24576);
        float4* db = (float4*)sWB;
        for (int i = tid; i < 6144; i += NT) db[i] = b4[i];
        float4 z = make_float4(0.f, 0.f, 0.f, 0.f);
        float4* z0 = (float4*)h0s; float4* z1 = (float4*)h1s;
        for (int i = tid; i < 2048; i += NT) { z0[i] = z; z1[i] = z; }
    }

    // per-thread gate constants (consumed by epilogue threads)
    float wi0[6], bi0[6], bh0[6], bi1c[6], bh1c[6];
#pragma unroll
    for (int q = 0; q < 6; q++) {
        int gate = q >> 1, cl = q & 1;
        int j = gate*256 + c0 + cl;
        wi0[q] = Wih0[j]; bi0[q] = bih0[j]; bh0[q] = bhh0[j];
        bi1c[q] = bih1[j]; bh1c[q] = bhh1[j];
    }
    __syncthreads();

    unsigned bar = 0;
    int par = 0;
    ull* const myred = red + (cp*16 + bp)*18;

    // ============ encoder: 512 merged phases (layer0 t=u, layer1 t=u-1) ============
    for (int u = 0; u < 512; u++) {
        ull aA[6], aI[6], aH[6];
#pragma unroll
        for (int i = 0; i < 6; i++) { aA[i] = 0ull; aI[i] = 0ull; aH[i] = 0ull; }
        {
            const float* h0p = h0s + 2*bp + kbeg*32;
            const float* h1p = h1s + 2*bp + kbeg*32;
            const float* wap = sWA + cp*6  + kbeg*48;
            const float* wbp = sWB + cp*12 + kbeg*96;
#pragma unroll 2
            for (int kk = 0; kk < 64; kk++) {
                float2 uu = *(const float2*)h0p;
                float2 vv = *(const float2*)h1p;
                ull ux = splat2(uu.x), uy = splat2(uu.y);
                ull vx = splat2(vv.x), vy = splat2(vv.y);
                const ull* wa = (const ull*)wap;
                ull a0 = wa[0], a1 = wa[1], a2 = wa[2];
                const ulonglong2* wb = (const ulonglong2*)wbp;
                ulonglong2 w0 = wb[0], w1 = wb[1], w2 = wb[2];
                fma2(aA[0], a0, ux);   fma2(aA[1], a0, uy);
                fma2(aA[2], a1, ux);   fma2(aA[3], a1, uy);
                fma2(aA[4], a2, ux);   fma2(aA[5], a2, uy);
                fma2(aI[0], w0.x, ux); fma2(aI[1], w0.x, uy);
                fma2(aH[0], w0.y, vx); fma2(aH[1], w0.y, vy);
                fma2(aI[2], w1.x, ux); fma2(aI[3], w1.x, uy);
                fma2(aH[2], w1.y, vx); fma2(aH[3], w1.y, vy);
                fma2(aI[4], w2.x, ux); fma2(aI[5], w2.x, uy);
                fma2(aH[4], w2.y, vx); fma2(aH[5], w2.y, vy);
                h0p += 32; h1p += 32; wap += 48; wbp += 96;
            }
        }
        // within-warp quarter-pair reduce
#pragma unroll
        for (int i = 0; i < 6; i++) { aA[i] = shred(aA[i]); aI[i] = shred(aI[i]); aH[i] = shred(aH[i]); }
        // cross-warp-half exchange
        if (kH == 1 && kh == 0) {
#pragma unroll
            for (int i = 0; i < 6; i++) { myred[i] = aA[i]; myred[6+i] = aI[i]; myred[12+i] = aH[i]; }
        }
        __syncthreads();

        if (epi) {
            // ---- layer0 epilogue: h0(u+1) ----
            {
                float2 xv2 = *(const float2*)(d_xT + u*256 + g*32 + 2*bp);
                float accA[12];
#pragma unroll
                for (int i = 0; i < 6; i++) {
                    float2 f = unp(add2(aA[i], myred[i]));
                    accA[i*2] = f.x; accA[i*2+1] = f.y;
                }
                float hv[2][2];
#pragma unroll
                for (int bl = 0; bl < 2; bl++) {
                    float xv = bl ? xv2.y : xv2.x;
#pragma unroll
                    for (int cl = 0; cl < 2; cl++) {
                        float gr = accA[0 + bl*2 + cl] + bh0[cl];
                        float gz = accA[4 + bl*2 + cl] + bh0[2 + cl];
                        float gn = accA[8 + bl*2 + cl] + bh0[4 + cl];
                        float r  = sigf(xv*wi0[cl]     + bi0[cl]     + gr);
                        float zz = sigf(xv*wi0[2 + cl] + bi0[2 + cl] + gz);
                        float n  = tanh_(xv*wi0[4 + cl] + bi0[4 + cl] + r*gn);
                        float hold = h0s[(c0 + cl)*32 + 2*bp + bl];
                        hv[bl][cl] = (1.0f - zz)*n + zz*hold;
                    }
                }
                float* dst = d_h0g + ((par*NG + g)*256 + c0)*32 + 2*bp;
                *(float2*)(dst)      = make_float2(hv[0][0], hv[1][0]);
                *(float2*)(dst + 32) = make_float2(hv[0][1], hv[1][1]);
            }
            // ---- layer1 epilogue: h1(u) (skip at u==0) ----
            if (u != 0) {
                float accI[12], accH[12];
#pragma unroll
                for (int i = 0; i < 6; i++) {
                    float2 fi = unp(add2(aI[i], myred[6+i]));
                    float2 fh = unp(add2(aH[i], myred[12+i]));
                    accI[i*2] = fi.x; accI[i*2+1] = fi.y;
                    accH[i*2] = fh.x; accH[i*2+1] = fh.y;
                }
                float hv[2][2];
#pragma unroll
                for (int bl = 0; bl < 2; bl++) {
#pragma unroll
                    for (int cl = 0; cl < 2; cl++) {
                        float ir  = accI[0 + bl*2 + cl] + bi1c[cl];
                        float iz  = accI[4 + bl*2 + cl] + bi1c[2 + cl];
                        float in_ = accI[8 + bl*2 + cl] + bi1c[4 + cl];
                        float hr  = accH[0 + bl*2 + cl] + bh1c[cl];
                        float hz  = accH[4 + bl*2 + cl] + bh1c[2 + cl];
                        float hn  = accH[8 + bl*2 + cl] + bh1c[4 + cl];
                        float r  = sigf(ir + hr);
                        float zz = sigf(iz + hz);
                        float n  = tanh_(in_ + r*hn);
                        float hold = h1s[(c0 + cl)*32 + 2*bp + bl];
                        hv[bl][cl] = (1.0f - zz)*n + zz*hold;
                    }
                }
                float* dst = d_h1g + ((par*NG + g)*256 + c0)*32 + 2*bp;
                *(float2*)(dst)      = make_float2(hv[0][0], hv[1][0]);
                *(float2*)(dst + 32) = make_float2(hv[0][1], hv[1][1]);
            }
        }

        bar++; gbar(g, bar*16);
        {   // refresh both h tiles
            const float4* s0 = (const float4*)(d_h0g + (par*NG + g)*8192);
            const float4* s1 = (const float4*)(d_h1g + (par*NG + g)*8192);
            float4* dd0 = (float4*)h0s; float4* dd1 = (float4*)h1s;
            for (int i = tid; i < 2048; i += NT) { dd0[i] = __ldcg(s0 + i); dd1[i] = __ldcg(s1 + i); }
        }
        __syncthreads();
        par ^= 1;
    }

    // ============ drain: layer1 step 511 -> h1(512) ============
    {
        ull aI[6], aH[6];
#pragma unroll
        for (int i = 0; i < 6; i++) { aI[i] = 0ull; aH[i] = 0ull; }
        const float* h0p = h0s + 2*bp + kbeg*32;
        const float* h1p = h1s + 2*bp + kbeg*32;
        const float* wbp = sWB + cp*12 + kbeg*96;
#pragma unroll 2
        for (int kk = 0; kk < 64; kk++) {
            float2 uu = *(const float2*)h0p;
            float2 vv = *(const float2*)h1p;
            ull ux = splat2(uu.x), uy = splat2(uu.y);
            ull vx = splat2(vv.x), vy = splat2(vv.y);
            const ulonglong2* wb = (const ulonglong2*)wbp;
            ulonglong2 w0 = wb[0], w1 = wb[1], w2 = wb[2];
            fma2(aI[0], w0.x, ux); fma2(aI[1], w0.x, uy);
            fma2(aH[0], w0.y, vx); fma2(aH[1], w0.y, vy);
            fma2(aI[2], w1.x, ux); fma2(aI[3], w1.x, uy);
            fma2(aH[2], w1.y, vx); fma2(aH[3], w1.y, vy);
            fma2(aI[4], w2.x, ux); fma2(aI[5], w2.x, uy);
            fma2(aH[4], w2.y, vx); fma2(aH[5], w2.y, vy);
            h0p += 32; h1p += 32; wbp += 96;
        }
#pragma unroll
        for (int i = 0; i < 6; i++) { aI[i] = shred(aI[i]); aH[i] = shred(aH[i]); }
        if (kH == 1 && kh == 0) {
#pragma unroll
            for (int i = 0; i < 6; i++) { myred[6+i] = aI[i]; myred[12+i] = aH[i]; }
        }
        __syncthreads();
        if (epi) {
            float accI[12], accH[12];
#pragma unroll
            for (int i = 0; i < 6; i++) {
                float2 fi = unp(add2(aI[i], myred[6+i]));
                float2 fh = unp(add2(aH[i], myred[12+i]));
                accI[i*2] = fi.x; accI[i*2+1] = fi.y;
                accH[i*2] = fh.x; accH[i*2+1] = fh.y;
            }
            float hv[2][2];
#pragma unroll
            for (int bl = 0; bl < 2; bl++) {
#pragma unroll
                for (int cl = 0; cl < 2; cl++) {
                    float ir  = accI[0 + bl*2 + cl] + bi1c[cl];
                    float iz  = accI[4 + bl*2 + cl] + bi1c[2 + cl];
                    float in_ = accI[8 + bl*2 + cl] + bi1c[4 + cl];
                    float hr  = accH[0 + bl*2 + cl] + bh1c[cl];
                    float hz  = accH[4 + bl*2 + cl] + bh1c[2 + cl];
                    float hn  = accH[8 + bl*2 + cl] + bh1c[4 + cl];
                    float r  = sigf(ir + hr);
                    float zz = sigf(iz + hz);
                    float n  = tanh_(in_ + r*hn);
                    float hold = h1s[(c0 + cl)*32 + 2*bp + bl];
                    hv[bl][cl] = (1.0f - zz)*n + zz*hold;
                }
            }
            float* dst = d_h1g + ((par*NG + g)*256 + c0)*32 + 2*bp;
            *(float2*)(dst)      = make_float2(hv[0][0], hv[1][0]);
            *(float2*)(dst + 32) = make_float2(hv[0][1], hv[1][1]);
        }
        bar++; gbar(g, bar*16);
        const float4* s1 = (const float4*)(d_h1g + (par*NG + g)*8192);
        float4* dd1 = (float4*)h1s;
        for (int i = tid; i < 2048; i += NT) dd1[i] = __ldcg(s1 + i);
        __syncthreads();
        par ^= 1;
    }

    // ============ decoder: 96 steps ============
    {   // overwrite sWA with packed Wd_hh
        const float4* a4 = (const float4*)(d_pD + p*12288);
        float4* da = (float4*)sWA;
        for (int i = tid; i < 3072; i += NT) da[i] = a4[i];
    }
    float wdi[6], bdi[6], bdh[6], wo0, wo1, bov;
#pragma unroll
    for (int q = 0; q < 6; q++) {
        int j = (q >> 1)*256 + c0 + (q & 1);
        wdi[q] = Wdih[j]; bdi[q] = bdih[j]; bdh[q] = bdhh[j];
    }
    wo0 = Wo[c0]; wo1 = Wo[c0 + 1]; bov = bo[0];
    float inp0 = 0.f, inp1 = 0.f;
    __syncthreads();

    for (int t = 0; t < 96; t++) {
        ull aD[6];
#pragma unroll
        for (int i = 0; i < 6; i++) aD[i] = 0ull;
        {
            const float* h1p = h1s + 2*bp + kbeg*32;
            const float* wap = sWA + cp*6 + kbeg*48;
#pragma unroll 4
            for (int kk = 0; kk < 64; kk++) {
                float2 vv = *(const float2*)h1p;
                ull vx = splat2(vv.x), vy = splat2(vv.y);
                const ull* wa = (const ull*)wap;
                ull a0 = wa[0], a1 = wa[1], a2 = wa[2];
                fma2(aD[0], a0, vx); fma2(aD[1], a0, vy);
                fma2(aD[2], a1, vx); fma2(aD[3], a1, vy);
                fma2(aD[4], a2, vx); fma2(aD[5], a2, vy);
                h1p += 32; wap += 48;
            }
        }
#pragma unroll
        for (int i = 0; i < 6; i++) aD[i] = shred(aD[i]);
        if (kH == 1 && kh == 0) {
#pragma unroll
            for (int i = 0; i < 6; i++) myred[i] = aD[i];
        }
        __syncthreads();

        float py0 = 0.f, py1 = 0.f;
        if (epi) {
            float acc[12];
#pragma unroll
            for (int i = 0; i < 6; i++) {
                float2 f = unp(add2(aD[i], myred[i]));
                acc[i*2] = f.x; acc[i*2+1] = f.y;
            }
            float hv[2][2];
#pragma unroll
            for (int bl = 0; bl < 2; bl++) {
                float inp = bl ? inp1 : inp0;
                float py = 0.f;
#pragma unroll
                for (int cl = 0; cl < 2; cl++) {
                    float gr = acc[0 + bl*2 + cl] + bdh[cl];
                    float gz = acc[4 + bl*2 + cl] + bdh[2 + cl];
                    float gn = acc[8 + bl*2 + cl] + bdh[4 + cl];
                    float r  = sigf(inp*wdi[cl]     + bdi[cl]     + gr);
                    float zz = sigf(inp*wdi[2 + cl] + bdi[2 + cl] + gz);
                    float n  = tanh_(inp*wdi[4 + cl] + bdi[4 + cl] + r*gn);
                    float hold = h1s[(c0 + cl)*32 + 2*bp + bl];
                    hv[bl][cl] = (1.0f - zz)*n + zz*hold;
                    py += hv[bl][cl] * (cl ? wo1 : wo0);
                }
                if (bl) py1 = py; else py0 = py;
            }
            float* dst = d_h1g + ((par*NG + g)*256 + c0)*32 + 2*bp;
            *(float2*)(dst)      = make_float2(hv[0][0], hv[1][0]);
            *(float2*)(dst + 32) = make_float2(hv[0][1], hv[1][1]);
        }
        __syncthreads();   // red fully consumed before red2 alias is written
        if (epi) {
            red2[(2*bp + 0)*8 + cp] = py0;
            red2[(2*bp + 1)*8 + cp] = py1;
        }
        __syncthreads();
        if (tid < 32) {    // per-batch partial over this CTA's 16 cols (fixed order)
            float s = 0.f;
#pragma unroll
            for (int j = 0; j < 8; j++) s += red2[tid*8 + j];
            d_partg[((par*NP + p)*NG + g)*32 + tid] = s;
        }
        bar++; gbar(g, bar*16);

        if (epi) {         // every epilogue thread reduces the 16 partials (fixed order)
            float s0 = bov, s1 = bov;
#pragma unroll
            for (int q = 0; q < 16; q++) {
                const float* pg = d_partg + ((par*NP + q)*NG + g)*32 + 2*bp;
                s0 += __ldcg(pg);
                s1 += __ldcg(pg + 1);
            }
            if (p == 0) {
                out[(g*32 + 2*bp    )*96 + t] = s0;
                out[(g*32 + 2*bp + 1)*96 + t] = s1;
            }
            inp0 = s0; inp1 = s1;
        }
        {   // refresh h1s <- h(t+1)
            const float4* src = (const float4*)(d_h1g + (par*NG + g)*8192);
            float4* dst = (float4*)h1s;
            for (int i = tid; i < 2048; i += NT) dst[i] = __ldcg(src + i);
        }
        __syncthreads();
        par ^= 1;
    }
}

// ---------------- launch ----------------
extern "C" void kernel_launch(void* const* d_in, const int* in_sizes, int n_in,
                              void* d_out, int out_size)
{
    const float* x    = (const float*)d_in[0];
    const float* Wih0 = (const float*)d_in[1];
    const float* Whh0 = (const float*)d_in[2];
    const float* bih0 = (const float*)d_in[3];
    const float* bhh0 = (const float*)d_in[4];
    const float* Wih1 = (const float*)d_in[5];
    const float* Whh1 = (const float*)d_in[6];
    const float* bih1 = (const float*)d_in[7];
    const float* bhh1 = (const float*)d_in[8];
    const float* Wdih = (const float*)d_in[9];
    const float* Wdhh = (const float*)d_in[10];
    const float* bdih = (const float*)d_in[11];
    const float* bdhh = (const float*)d_in[12];
    const float* Wo   = (const float*)d_in[13];
    const float* bo   = (const float*)d_in[14];
    float* out = (float*)d_out;

    cudaFuncSetAttribute(gru_main, cudaFuncAttributeMaxDynamicSharedMemorySize, SMEM_BYTES);
    prep_kernel<<<384, 256>>>(Whh0, Wih1, Whh1, Wdhh, x);
    gru_main<<<NBLK, NT, SMEM_BYTES>>>(Wih0, bih0, bhh0, bih1, bhh1,
                                       Wdih, bdih, bdhh, Wo, bo, out);
}

// round 13
// speedup vs baseline: 1.1167x; 1.1167x over previous
#include <cuda_runtime.h>

typedef unsigned long long ull;

#define NG 8           // batch groups (32 batches each)
#define NP 16          // column partitions (16 hidden cols each)
#define NBLK (NG*NP)   // 128 CTAs
#define NT 256         // 8 warps
// smem floats: sWA 12800 (pad 50/row) + sWB 25600 (pad 100/row) + h0s 8192 + h1s 8192 + red2 256 + ybuf 32
#define SM_FLOATS (12800+25600+8192+8192+256+32)
#define SMEM_BYTES (SM_FLOATS*4)

// ---------------- static device scratch (no allocation) ----------------
__device__ float d_pA[NP*256*50];      // W_hh0 packed  [p][k(stride50)][cp][gate*2+cl]
__device__ float d_pB[NP*256*100];     // W_ih1|W_hh1   [p][k(stride100)][cp][gate*4+s*2+cl]
__device__ float d_pD[NP*256*50];      // Wd_hh packed like A
__device__ float d_xT[512*256];        // x transposed [t][b]
__device__ float d_h0g[2*NG*256*32];   // double-buffered layer0 h [par][g][col][b]
__device__ float d_h1g[2*NG*256*32];   // layer1 / decoder h
__device__ float d_partg[2*NP*NG*32];  // decoder partial y
__device__ unsigned int d_cnt[NG];     // group barrier counters

// ---------------- prep: reset barriers, pack (padded) weights, transpose x ----------------
__global__ void prep_kernel(const float* __restrict__ Whh0, const float* __restrict__ Wih1,
                            const float* __restrict__ Whh1, const float* __restrict__ Wdhh,
                            const float* __restrict__ x)
{
    int idx = blockIdx.x*blockDim.x + threadIdx.x;
    int stride = gridDim.x*blockDim.x;
    if (idx < NG) d_cnt[idx] = 0u;
    for (int i = idx; i < NP*256*48; i += stride) {
        int q = i % 6, cp = (i/6) & 7, k = (i/48) & 255, p = i/12288;
        int gate = q >> 1, cl = q & 1;
        int col = p*16 + cp*2 + cl;
        int src = (gate*256 + col)*256 + k;
        int dst = p*12800 + k*50 + cp*6 + q;
        d_pA[dst] = Whh0[src];
        d_pD[dst] = Wdhh[src];
    }
    for (int i = idx; i < NP*256*96; i += stride) {
        int q = i % 12, cp = (i/12) & 7, k = (i/96) & 255, p = i/24576;
        int gate = q >> 2, s = (q >> 1) & 1, cl = q & 1;
        int col = p*16 + cp*2 + cl;
        int src = (gate*256 + col)*256 + k;
        d_pB[p*25600 + k*100 + cp*12 + q] = s ? Whh1[src] : Wih1[src];
    }
    for (int i = idx; i < 512*256; i += stride)
        d_xT[i] = x[(i & 255)*512 + (i >> 8)];
    for (int i = idx; i < 2*NG*256*32; i += stride)
        d_h1g[i] = 0.0f;   // phase-0 refresh of h1 must read zeros
}

// ---------------- helpers ----------------
__device__ __forceinline__ ull splat2(float v){ ull r; asm("mov.b64 %0, {%1,%1};" : "=l"(r) : "f"(v)); return r; }
__device__ __forceinline__ void fma2(ull &d, ull a, ull b){ asm("fma.rn.f32x2 %0, %1, %2, %0;" : "+l"(d) : "l"(a), "l"(b)); }
__device__ __forceinline__ ull add2(ull a, ull b){ ull r; asm("add.rn.f32x2 %0, %1, %2;" : "=l"(r) : "l"(a), "l"(b)); return r; }
__device__ __forceinline__ float2 unp(ull v){ float2 f; asm("mov.b64 {%0,%1}, %2;" : "=f"(f.x), "=f"(f.y) : "l"(v)); return f; }
__device__ __forceinline__ float sigf(float v){ return 1.0f/(1.0f + __expf(-v)); }
__device__ __forceinline__ float tanh_(float v){
    float a = fabsf(v), e = __expf(-2.0f*a);
    float t = (1.0f - e)/(1.0f + e);
    return v < 0.0f ? -t : t;
}
// 4-way k-offset reduce, fully in-warp (kh = lane>>3): ((0+1)+(2+3)) fixed order
__device__ __forceinline__ ull shred(ull v){
    v = add2(v, __shfl_xor_sync(0xffffffffu, v, 8));
    v = add2(v, __shfl_xor_sync(0xffffffffu, v, 16));
    return v;
}

// per-group barrier: release(prior stores) -> arrive -> spin -> acquire
__device__ __forceinline__ void gbar(int g, unsigned target){
    __threadfence();
    __syncthreads();
    if (threadIdx.x == 0) {
        atomicAdd(&d_cnt[g], 1u);
        while (*(volatile unsigned*)&d_cnt[g] < target) __nanosleep(16);
        __threadfence();
    }
    __syncthreads();
}

// ---------------- main persistent kernel ----------------
__global__ __launch_bounds__(NT, 1) void gru_main(
    const float* __restrict__ Wih0, const float* __restrict__ bih0, const float* __restrict__ bhh0,
    const float* __restrict__ bih1, const float* __restrict__ bhh1,
    const float* __restrict__ Wdih, const float* __restrict__ bdih, const float* __restrict__ bdhh,
    const float* __restrict__ Wo, const float* __restrict__ bo,
    float* __restrict__ out)
{
    extern __shared__ float sm[];
    float* sWA  = sm;                      // [256][50]  12800 (8 cp x 6 used)
    float* sWB  = sm + 12800;              // [256][100] 25600 (8 cp x 12 used)
    float* h0s  = sWB + 25600;             // [256 col][32 b]  8192
    float* h1s  = h0s + 8192;              // [256][32]        8192
    float* red2 = h1s + 8192;              // [32 b][8 cp]      256
    float* ybuf = red2 + 256;              //                    32

    const int p    = blockIdx.x & 15;
    const int g    = blockIdx.x >> 4;
    const int tid  = threadIdx.x;
    const int cp   = tid >> 5;             // warp = col pair 0..7
    const int lane = tid & 31;
    const int bq   = lane & 7;             // batch quad 0..7 (4 batches each)
    const int kh   = lane >> 3;            // k offset 0..3
    const int c0   = p*16 + cp*2;
    const bool epi = (kh == 0);            // 64 epilogue threads (8 per warp)

    // stage weights + zero h tiles
    {
        const float4* a4 = (const float4*)(d_pA + p*12800);
        float4* da = (float4*)sWA;
        for (int i = tid; i < 3200; i += NT) da[i] = a4[i];
        const float4* b4 = (const float4*)(d_pB + p*25600);
        float4* db = (float4*)sWB;
        for (int i = tid; i < 6400; i += NT) db[i] = b4[i];
        float4 z = make_float4(0.f, 0.f, 0.f, 0.f);
        float4* z0 = (float4*)h0s; float4* z1 = (float4*)h1s;
        for (int i = tid; i < 2048; i += NT) { z0[i] = z; z1[i] = z; }
    }

    // per-thread gate constants (consumed by epilogue threads); q = gate*2+cl
    float wi0[6], bi0[6], bh0[6], bi1c[6], bh1c[6];
#pragma unroll
    for (int q = 0; q < 6; q++) {
        int j = (q >> 1)*256 + c0 + (q & 1);
        wi0[q] = Wih0[j]; bi0[q] = bih0[j]; bh0[q] = bhh0[j];
        bi1c[q] = bih1[j]; bh1c[q] = bhh1[j];
    }
    __syncthreads();

    unsigned bar = 0;
    int par = 0;

    // ============ encoder: 512 merged phases (layer0 t=u, layer1 t=u-1) ============
    for (int u = 0; u < 512; u++) {
        ull aA[12], aI[12], aH[12];     // [gate*4 + bl], packed over 2 cols
#pragma unroll
        for (int i = 0; i < 12; i++) { aA[i] = 0ull; aI[i] = 0ull; aH[i] = 0ull; }
        {
            const float* h0p = h0s + bq*4 + kh*32;
            const float* h1p = h1s + bq*4 + kh*32;
            const float* wap = sWA + kh*50  + cp*6;
            const float* wbp = sWB + kh*100 + cp*12;
#pragma unroll 4
            for (int kk = 0; kk < 64; kk++) {
                float4 u4 = *(const float4*)h0p;
                float4 v4 = *(const float4*)h1p;
                const ull* wa = (const ull*)wap;
                ull a0 = wa[0], a1 = wa[1], a2 = wa[2];
                const ulonglong2* wb = (const ulonglong2*)wbp;
                ulonglong2 w0 = wb[0], w1 = wb[1], w2 = wb[2];
                const float* uf = (const float*)&u4;
                const float* vf = (const float*)&v4;
#pragma unroll
                for (int bl = 0; bl < 4; bl++) {
                    ull hx = splat2(uf[bl]);
                    fma2(aA[0+bl], a0, hx);
                    fma2(aA[4+bl], a1, hx);
                    fma2(aA[8+bl], a2, hx);
                    fma2(aI[0+bl], w0.x, hx);
                    fma2(aI[4+bl], w1.x, hx);
                    fma2(aI[8+bl], w2.x, hx);
                    ull vx = splat2(vf[bl]);
                    fma2(aH[0+bl], w0.y, vx);
                    fma2(aH[4+bl], w1.y, vx);
                    fma2(aH[8+bl], w2.y, vx);
                }
                h0p += 128; h1p += 128; wap += 200; wbp += 400;
            }
        }
        // in-warp k reduce
#pragma unroll
        for (int i = 0; i < 12; i++) { aA[i] = shred(aA[i]); aI[i] = shred(aI[i]); aH[i] = shred(aH[i]); }

        if (epi) {
            // ---- layer0 epilogue: h0(u+1) ----
            {
                float4 xv4 = *(const float4*)(d_xT + u*256 + g*32 + bq*4);
                const float* xf = (const float*)&xv4;
                float hv0[4], hv1[4];
#pragma unroll
                for (int bl = 0; bl < 4; bl++) {
                    float xv = xf[bl];
                    float2 fr = unp(aA[0+bl]);
                    float2 fz = unp(aA[4+bl]);
                    float2 fn = unp(aA[8+bl]);
                    {
                        float gr = fr.x + bh0[0];
                        float gz = fz.x + bh0[2];
                        float gn = fn.x + bh0[4];
                        float r  = sigf(xv*wi0[0] + bi0[0] + gr);
                        float zz = sigf(xv*wi0[2] + bi0[2] + gz);
                        float n  = tanh_(xv*wi0[4] + bi0[4] + r*gn);
                        float hold = h0s[c0*32 + bq*4 + bl];
                        hv0[bl] = (1.0f - zz)*n + zz*hold;
                    }
                    {
                        float gr = fr.y + bh0[1];
                        float gz = fz.y + bh0[3];
                        float gn = fn.y + bh0[5];
                        float r  = sigf(xv*wi0[1] + bi0[1] + gr);
                        float zz = sigf(xv*wi0[3] + bi0[3] + gz);
                        float n  = tanh_(xv*wi0[5] + bi0[5] + r*gn);
                        float hold = h0s[(c0+1)*32 + bq*4 + bl];
                        hv1[bl] = (1.0f - zz)*n + zz*hold;
                    }
                }
                float* dst = d_h0g + ((par*NG + g)*256 + c0)*32 + bq*4;
                *(float4*)dst        = make_float4(hv0[0], hv0[1], hv0[2], hv0[3]);
                *(float4*)(dst + 32) = make_float4(hv1[0], hv1[1], hv1[2], hv1[3]);
            }
            // ---- layer1 epilogue: h1(u) (skip at u==0) ----
            if (u != 0) {
                float hv0[4], hv1[4];
#pragma unroll
                for (int bl = 0; bl < 4; bl++) {
                    float2 fIr = unp(aI[0+bl]);
                    float2 fIz = unp(aI[4+bl]);
                    float2 fIn = unp(aI[8+bl]);
                    float2 fHr = unp(aH[0+bl]);
                    float2 fHz = unp(aH[4+bl]);
                    float2 fHn = unp(aH[8+bl]);
                    {
                        float r  = sigf(fIr.x + bi1c[0] + fHr.x + bh1c[0]);
                        float zz = sigf(fIz.x + bi1c[2] + fHz.x + bh1c[2]);
                        float n  = tanh_(fIn.x + bi1c[4] + r*(fHn.x + bh1c[4]));
                        float hold = h1s[c0*32 + bq*4 + bl];
                        hv0[bl] = (1.0f - zz)*n + zz*hold;
                    }
                    {
                        float r  = sigf(fIr.y + bi1c[1] + fHr.y + bh1c[1]);
                        float zz = sigf(fIz.y + bi1c[3] + fHz.y + bh1c[3]);
                        float n  = tanh_(fIn.y + bi1c[5] + r*(fHn.y + bh1c[5]));
                        float hold = h1s[(c0+1)*32 + bq*4 + bl];
                        hv1[bl] = (1.0f - zz)*n + zz*hold;
                    }
                }
                float* dst = d_h1g + ((par*NG + g)*256 + c0)*32 + bq*4;
                *(float4*)dst        = make_float4(hv0[0], hv0[1], hv0[2], hv0[3]);
                *(float4*)(dst + 32) = make_float4(hv1[0], hv1[1], hv1[2], hv1[3]);
            }
        }

        bar++; gbar(g, bar*16);
        {   // refresh both h tiles
            const float4* s0 = (const float4*)(d_h0g + (par*NG + g)*8192);
            const float4* s1 = (const float4*)(d_h1g + (par*NG + g)*8192);
            float4* dd0 = (float4*)h0s; float4* dd1 = (float4*)h1s;
            for (int i = tid; i < 2048; i += NT) { dd0[i] = __ldcg(s0 + i); dd1[i] = __ldcg(s1 + i); }
        }
        __syncthreads();
        par ^= 1;
    }

    // ============ drain: layer1 step 511 -> h1(512) ============
    {
        ull aI[12], aH[12];
#pragma unroll
        for (int i = 0; i < 12; i++) { aI[i] = 0ull; aH[i] = 0ull; }
        {
            const float* h0p = h0s + bq*4 + kh*32;
            const float* h1p = h1s + bq*4 + kh*32;
            const float* wbp = sWB + kh*100 + cp*12;
#pragma unroll 4
            for (int kk = 0; kk < 64; kk++) {
                float4 u4 = *(const float4*)h0p;
                float4 v4 = *(const float4*)h1p;
                const ulonglong2* wb = (const ulonglong2*)wbp;
                ulonglong2 w0 = wb[0], w1 = wb[1], w2 = wb[2];
                const float* uf = (const float*)&u4;
                const float* vf = (const float*)&v4;
#pragma unroll
                for (int bl = 0; bl < 4; bl++) {
                    ull hx = splat2(uf[bl]);
                    fma2(aI[0+bl], w0.x, hx);
                    fma2(aI[4+bl], w1.x, hx);
                    fma2(aI[8+bl], w2.x, hx);
                    ull vx = splat2(vf[bl]);
                    fma2(aH[0+bl], w0.y, vx);
                    fma2(aH[4+bl], w1.y, vx);
                    fma2(aH[8+bl], w2.y, vx);
                }
                h0p += 128; h1p += 128; wbp += 400;
            }
        }
#pragma unroll
        for (int i = 0; i < 12; i++) { aI[i] = shred(aI[i]); aH[i] = shred(aH[i]); }
        if (epi) {
            float hv0[4], hv1[4];
#pragma unroll
            for (int bl = 0; bl < 4; bl++) {
                float2 fIr = unp(aI[0+bl]);
                float2 fIz = unp(aI[4+bl]);
                float2 fIn = unp(aI[8+bl]);
                float2 fHr = unp(aH[0+bl]);
                float2 fHz = unp(aH[4+bl]);
                float2 fHn = unp(aH[8+bl]);
                {
                    float r  = sigf(fIr.x + bi1c[0] + fHr.x + bh1c[0]);
                    float zz = sigf(fIz.x + bi1c[2] + fHz.x + bh1c[2]);
                    float n  = tanh_(fIn.x + bi1c[4] + r*(fHn.x + bh1c[4]));
                    float hold = h1s[c0*32 + bq*4 + bl];
                    hv0[bl] = (1.0f - zz)*n + zz*hold;
                }
                {
                    float r  = sigf(fIr.y + bi1c[1] + fHr.y + bh1c[1]);
                    float zz = sigf(fIz.y + bi1c[3] + fHz.y + bh1c[3]);
                    float n  = tanh_(fIn.y + bi1c[5] + r*(fHn.y + bh1c[5]));
                    float hold = h1s[(c0+1)*32 + bq*4 + bl];
                    hv1[bl] = (1.0f - zz)*n + zz*hold;
                }
            }
            float* dst = d_h1g + ((par*NG + g)*256 + c0)*32 + bq*4;
            *(float4*)dst        = make_float4(hv0[0], hv0[1], hv0[2], hv0[3]);
            *(float4*)(dst + 32) = make_float4(hv1[0], hv1[1], hv1[2], hv1[3]);
        }
        bar++; gbar(g, bar*16);
        const float4* s1 = (const float4*)(d_h1g + (par*NG + g)*8192);
        float4* dd1 = (float4*)h1s;
        for (int i = tid; i < 2048; i += NT) dd1[i] = __ldcg(s1 + i);
        __syncthreads();
        par ^= 1;
    }

    // ============ decoder: 96 steps ============
    {   // overwrite sWA with packed Wd_hh
        const float4* a4 = (const float4*)(d_pD + p*12800);
        float4* da = (float4*)sWA;
        for (int i = tid; i < 3200; i += NT) da[i] = a4[i];
    }
    float wdi[6], bdi[6], bdh[6], wo0, wo1, bov;
#pragma unroll
    for (int q = 0; q < 6; q++) {
        int j = (q >> 1)*256 + c0 + (q & 1);
        wdi[q] = Wdih[j]; bdi[q] = bdih[j]; bdh[q] = bdhh[j];
    }
    wo0 = Wo[c0]; wo1 = Wo[c0 + 1]; bov = bo[0];
    float inp[4] = {0.f, 0.f, 0.f, 0.f};
    __syncthreads();

    for (int t = 0; t < 96; t++) {
        ull aD[12];
#pragma unroll
        for (int i = 0; i < 12; i++) aD[i] = 0ull;
        {
            const float* h1p = h1s + bq*4 + kh*32;
            const float* wap = sWA + kh*50 + cp*6;
#pragma unroll 4
            for (int kk = 0; kk < 64; kk++) {
                float4 v4 = *(const float4*)h1p;
                const ull* wa = (const ull*)wap;
                ull a0 = wa[0], a1 = wa[1], a2 = wa[2];
                const float* vf = (const float*)&v4;
#pragma unroll
                for (int bl = 0; bl < 4; bl++) {
                    ull vx = splat2(vf[bl]);
                    fma2(aD[0+bl], a0, vx);
                    fma2(aD[4+bl], a1, vx);
                    fma2(aD[8+bl], a2, vx);
                }
                h1p += 128; wap += 200;
            }
        }
#pragma unroll
        for (int i = 0; i < 12; i++) aD[i] = shred(aD[i]);

        if (epi) {
            float hv0[4], hv1[4];
#pragma unroll
            for (int bl = 0; bl < 4; bl++) {
                float iv = inp[bl];
                float2 fr = unp(aD[0+bl]);
                float2 fz = unp(aD[4+bl]);
                float2 fn = unp(aD[8+bl]);
                {
                    float gr = fr.x + bdh[0];
                    float gz = fz.x + bdh[2];
                    float gn = fn.x + bdh[4];
                    float r  = sigf(iv*wdi[0] + bdi[0] + gr);
                    float zz = sigf(iv*wdi[2] + bdi[2] + gz);
                    float n  = tanh_(iv*wdi[4] + bdi[4] + r*gn);
                    float hold = h1s[c0*32 + bq*4 + bl];
                    hv0[bl] = (1.0f - zz)*n + zz*hold;
                }
                {
                    float gr = fr.y + bdh[1];
                    float gz = fz.y + bdh[3];
                    float gn = fn.y + bdh[5];
                    float r  = sigf(iv*wdi[1] + bdi[1] + gr);
                    float zz = sigf(iv*wdi[3] + bdi[3] + gz);
                    float n  = tanh_(iv*wdi[5] + bdi[5] + r*gn);
                    float hold = h1s[(c0+1)*32 + bq*4 + bl];
                    hv1[bl] = (1.0f - zz)*n + zz*hold;
                }
                red2[(bq*4 + bl)*8 + cp] = hv0[bl]*wo0 + hv1[bl]*wo1;
            }
            float* dst = d_h1g + ((par*NG + g)*256 + c0)*32 + bq*4;
            *(float4*)dst        = make_float4(hv0[0], hv0[1], hv0[2], hv0[3]);
            *(float4*)(dst + 32) = make_float4(hv1[0], hv1[1], hv1[2], hv1[3]);
        }
        __syncthreads();
        if (tid < 32) {    // per-batch partial over this CTA's 16 cols (fixed order)
            float s = 0.f;
#pragma unroll
            for (int j = 0; j < 8; j++) s += red2[tid*8 + j];
            d_partg[((par*NP + p)*NG + g)*32 + tid] = s;
        }
        bar++; gbar(g, bar*16);

        if (tid < 32) {    // deterministic final sum; every CTA computes, p==0 writes out
            float s = bov;
#pragma unroll
            for (int q = 0; q < 16; q++)
                s += __ldcg(&d_partg[((par*NP + q)*NG + g)*32 + tid]);
            ybuf[tid] = s;
            if (p == 0) out[(g*32 + tid)*96 + t] = s;
        }
        {   // refresh h1s <- h(t+1)
            const float4* src = (const float4*)(d_h1g + (par*NG + g)*8192);
            float4* dst = (float4*)h1s;
            for (int i = tid; i < 2048; i += NT) dst[i] = __ldcg(src + i);
        }
        __syncthreads();
        if (epi) {
#pragma unroll
            for (int bl = 0; bl < 4; bl++) inp[bl] = ybuf[bq*4 + bl];
        }
        par ^= 1;
    }
}

// ---------------- launch ----------------
extern "C" void kernel_launch(void* const* d_in, const int* in_sizes, int n_in,
                              void* d_out, int out_size)
{
    const float* x    = (const float*)d_in[0];
    const float* Wih0 = (const float*)d_in[1];
    const float* Whh0 = (const float*)d_in[2];
    const float* bih0 = (const float*)d_in[3];
    const float* bhh0 = (const float*)d_in[4];
    const float* Wih1 = (const float*)d_in[5];
    const float* Whh1 = (const float*)d_in[6];
    const float* bih1 = (const float*)d_in[7];
    const float* bhh1 = (const float*)d_in[8];
    const float* Wdih = (const float*)d_in[9];
    const float* Wdhh = (const float*)d_in[10];
    const float* bdih = (const float*)d_in[11];
    const float* bdhh = (const float*)d_in[12];
    const float* Wo   = (const float*)d_in[13];
    const float* bo   = (const float*)d_in[14];
    float* out = (float*)d_out;

    cudaFuncSetAttribute(gru_main, cudaFuncAttributeMaxDynamicSharedMemorySize, SMEM_BYTES);
    prep_kernel<<<384, 256>>>(Whh0, Wih1, Whh1, Wdhh, x);
    gru_main<<<NBLK, NT, SMEM_BYTES>>>(Wih0, bih0, bhh0, bih1, bhh1,
                                       Wdih, bdih, bdhh, Wo, bo, out);
}